// round 8
// baseline (speedup 1.0000x reference)
#include <cuda_runtime.h>
#include <math.h>

// Scratch (no cudaMalloc allowed; zero-initialized)
__device__ float g_feats[32 * 1280];        // [B, (K+1)*C] pooled means
__device__ float g_w1[32 * 256];            // [B, C] sigmoid self-gate
__device__ float g_w2[32 * 4 * 256];        // [B, K, C] softmax branch gates
__device__ unsigned int g_cnt1[32];         // means-done tickets
__device__ unsigned int g_cnt2[32];         // apply-done tickets (for reset)
__device__ volatile unsigned int g_flag[32];// gate-ready flags

#define B_ 32
#define C_ 256
#define K_ 4
#define HW_ 1024
#define MID_ 32
#define FEAT_ 1280       // (K+1)*C
#define SUBS_ 64         // blocks per batch
#define THREADS_ 512
#define ROWS_PB_ 20      // means rows per block (1280/64)

__global__ void __launch_bounds__(THREADS_, 2)
k_fused(const float* __restrict__ y,
        const float* __restrict__ x0,
        const float* __restrict__ x1,
        const float* __restrict__ x2,
        const float* __restrict__ x3,
        const float* __restrict__ conv1_w,   // [32,1280]
        const float* __restrict__ bn_gamma,
        const float* __restrict__ bn_beta,
        const float* __restrict__ bn_mean,
        const float* __restrict__ bn_var,
        const float* __restrict__ conv2_w,   // [1280,32]
        const float* __restrict__ conv2_b,   // [1280]
        float* __restrict__ out) {
    int bid = blockIdx.x;
    int b   = bid >> 6;          // batch
    int sub = bid & (SUBS_ - 1); // 0..63 within batch
    int t   = threadIdx.x;
    int w   = t >> 5, lane = t & 31;

    // Early distributed L2 prefetch of weights (2560 lines) by first 5 blocks.
    if (bid < 5) {
        int l = bid * THREADS_ + t;           // 0..2559
        const float* p = (l < 1280) ? conv1_w + l * 32
                                    : conv2_w + (l - 1280) * 32;
        asm volatile("prefetch.global.L2 [%0];" :: "l"(p));
    }

    // ---------------- Phase 1: means for this block's 20 rows ----------------
#pragma unroll
    for (int pass = 0; pass < 2; pass++) {
        int rr = pass * 16 + w;
        if (rr < ROWS_PB_) {
            int j = sub * ROWS_PB_ + rr;      // 0..1279 within batch
            int slot = j >> 8;
            int c = j & 255;
            const float* base;
            switch (slot) {
                case 0: base = y;  break;
                case 1: base = x0; break;
                case 2: base = x1; break;
                case 3: base = x2; break;
                default: base = x3; break;
            }
            const float4* p = reinterpret_cast<const float4*>(
                base + (size_t)(b * C_ + c) * HW_);
            float s = 0.f;
#pragma unroll
            for (int i = 0; i < 8; i++) {
                float4 v = p[lane + i * 32];
                s += (v.x + v.y) + (v.z + v.w);
            }
#pragma unroll
            for (int o = 16; o; o >>= 1) s += __shfl_xor_sync(0xffffffffu, s, o);
            if (lane == 0) {
                g_feats[b * FEAT_ + j] = s * (1.0f / 1024.0f);
                __threadfence();              // release this row's write
            }
        }
    }
    __syncthreads();

    __shared__ unsigned int ticket;
    if (t == 0) ticket = atomicAdd(&g_cnt1[b], 1u);
    __syncthreads();

    // ---------------- Phase 2: last block of batch computes the gate MLP ------
    __shared__ float sf[FEAT_];
    __shared__ float sh[MID_];
    __shared__ float sv[FEAT_];
    if (ticket == SUBS_ - 1) {
        __threadfence();                      // acquire siblings' feats writes
        for (int i = t; i < FEAT_; i += THREADS_) sf[i] = g_feats[b * FEAT_ + i];
        __syncthreads();

        // GEMM1: warp w handles mids {2w, 2w+1}
#pragma unroll
        for (int mi = 0; mi < 2; mi++) {
            int mid = w * 2 + mi;
            const float* wr = conv1_w + mid * FEAT_;
            float s = 0.f;
#pragma unroll
            for (int j0 = 0; j0 < FEAT_; j0 += 32)
                s = fmaf(sf[j0 + lane], wr[j0 + lane], s);
#pragma unroll
            for (int o = 16; o; o >>= 1) s += __shfl_xor_sync(0xffffffffu, s, o);
            if (lane == 0) {
                float hv = (s - bn_mean[mid]) *
                           (bn_gamma[mid] * rsqrtf(bn_var[mid] + 1e-5f)) +
                           bn_beta[mid];
                sh[mid] = fmaxf(hv, 0.f);
            }
        }
        __syncthreads();

        // GEMM2: 1280 outputs over 512 threads (chunks t, t+512, t+1024)
        {
            int j = t;
            float s = conv2_b[j];
            const float* wr = conv2_w + j * MID_;
#pragma unroll
            for (int m = 0; m < MID_; m++) s = fmaf(sh[m], wr[m], s);
            sv[j] = s;
        }
        {
            int j = t + 512;
            float s = conv2_b[j];
            const float* wr = conv2_w + j * MID_;
#pragma unroll
            for (int m = 0; m < MID_; m++) s = fmaf(sh[m], wr[m], s);
            sv[j] = s;
        }
        if (t < FEAT_ - 1024) {
            int j = t + 1024;
            float s = conv2_b[j];
            const float* wr = conv2_w + j * MID_;
#pragma unroll
            for (int m = 0; m < MID_; m++) s = fmaf(sh[m], wr[m], s);
            sv[j] = s;
        }
        __syncthreads();

        if (t < C_) {
            float v0 = sv[t];
            float v1 = sv[256 + t], v2 = sv[512 + t];
            float v3 = sv[768 + t], v4 = sv[1024 + t];
            g_w1[b * C_ + t] = 1.0f / (1.0f + expf(-v0));
            float mx = fmaxf(fmaxf(v1, v2), fmaxf(v3, v4));
            float e1 = expf(v1 - mx), e2 = expf(v2 - mx);
            float e3 = expf(v3 - mx), e4 = expf(v4 - mx);
            float inv = 1.0f / (e1 + e2 + e3 + e4);
            int gb = b * K_ * C_ + t;
            g_w2[gb + 0 * C_] = e1 * inv;
            g_w2[gb + 1 * C_] = e2 * inv;
            g_w2[gb + 2 * C_] = e3 * inv;
            g_w2[gb + 3 * C_] = e4 * inv;
            __threadfence();                  // release gate writes
        }
        __syncthreads();
        if (t == 0) g_flag[b] = 1;            // publish (ordered after fences via bar)
    }

    // ---------------- Phase 3: wait for this batch's gates ----------------
    if (t == 0) {
        while (g_flag[b] == 0) __nanosleep(64);
        __threadfence();                      // acquire gate writes
    }
    __syncthreads();

    // ---------------- Phase 4: apply gates to this block's 4 output rows -----
    {
        int c = sub * 4 + (t >> 7);           // 4 rows per block
        int g = t & 127;                      // 128 threads per row
        float w1 = g_w1[b * C_ + c];
        int gb = b * K_ * C_ + c;
        float a0 = g_w2[gb + 0 * C_];
        float a1 = g_w2[gb + 1 * C_];
        float a2 = g_w2[gb + 2 * C_];
        float a3 = g_w2[gb + 3 * C_];

        size_t row = (size_t)(b * C_ + c) * 256;   // float4 units
        size_t i0 = row + g;
        size_t i1 = i0 + 128;

        const float4* Y  = reinterpret_cast<const float4*>(y);
        const float4* X0 = reinterpret_cast<const float4*>(x0);
        const float4* X1 = reinterpret_cast<const float4*>(x1);
        const float4* X2 = reinterpret_cast<const float4*>(x2);
        const float4* X3 = reinterpret_cast<const float4*>(x3);

        float4 ya = Y[i0],  yb = Y[i1];
        float4 p0 = X0[i0], q0 = X0[i1];
        float4 p1 = X1[i0], q1 = X1[i1];
        float4 p2 = X2[i0], q2 = X2[i1];
        float4 p3 = X3[i0], q3 = X3[i1];

        float4 r;
        r.x = fmaf(ya.x, w1, fmaf(a0, p0.x, fmaf(a1, p1.x, fmaf(a2, p2.x, a3 * p3.x))));
        r.y = fmaf(ya.y, w1, fmaf(a0, p0.y, fmaf(a1, p1.y, fmaf(a2, p2.y, a3 * p3.y))));
        r.z = fmaf(ya.z, w1, fmaf(a0, p0.z, fmaf(a1, p1.z, fmaf(a2, p2.z, a3 * p3.z))));
        r.w = fmaf(ya.w, w1, fmaf(a0, p0.w, fmaf(a1, p1.w, fmaf(a2, p2.w, a3 * p3.w))));
        __stcs(reinterpret_cast<float4*>(out) + i0, r);

        float4 s;
        s.x = fmaf(yb.x, w1, fmaf(a0, q0.x, fmaf(a1, q1.x, fmaf(a2, q2.x, a3 * q3.x))));
        s.y = fmaf(yb.y, w1, fmaf(a0, q0.y, fmaf(a1, q1.y, fmaf(a2, q2.y, a3 * q3.y))));
        s.z = fmaf(yb.z, w1, fmaf(a0, q0.z, fmaf(a1, q1.z, fmaf(a2, q2.z, a3 * q3.z))));
        s.w = fmaf(yb.w, w1, fmaf(a0, q0.w, fmaf(a1, q1.w, fmaf(a2, q2.w, a3 * q3.w))));
        __stcs(reinterpret_cast<float4*>(out) + i1, s);
    }

    // ---------------- Reset counters/flags for next graph replay ----------------
    if (t == 0) {
        unsigned int k2 = atomicAdd(&g_cnt2[b], 1u);
        if (k2 == SUBS_ - 1) {                // all siblings past the spin
            g_cnt1[b] = 0;
            g_cnt2[b] = 0;
            g_flag[b] = 0;
        }
    }
}

extern "C" void kernel_launch(void* const* d_in, const int* in_sizes, int n_in,
                              void* d_out, int out_size) {
    const float* y       = (const float*)d_in[0];
    const float* x0      = (const float*)d_in[1];
    const float* x1      = (const float*)d_in[2];
    const float* x2      = (const float*)d_in[3];
    const float* x3      = (const float*)d_in[4];
    const float* conv1_w = (const float*)d_in[5];
    const float* bn_g    = (const float*)d_in[6];
    const float* bn_b    = (const float*)d_in[7];
    const float* bn_m    = (const float*)d_in[8];
    const float* bn_v    = (const float*)d_in[9];
    const float* conv2_w = (const float*)d_in[10];
    const float* conv2_b = (const float*)d_in[11];
    float* out = (float*)d_out;

    // 32 batches x 64 blocks = 2048 blocks, 512 threads
    k_fused<<<32 * SUBS_, THREADS_>>>(y, x0, x1, x2, x3,
                                      conv1_w, bn_g, bn_b, bn_m, bn_v,
                                      conv2_w, conv2_b, out);
}

// round 9
// speedup vs baseline: 4.3508x; 4.3508x over previous
#include <cuda_runtime.h>
#include <math.h>

// Scratch (no cudaMalloc allowed)
__device__ float g_feats[32 * 1280];   // [B, (K+1)*C] pooled means
__device__ float g_h[32 * 32];         // [MID][B] hidden after BN+ReLU (transposed)
__device__ float g_w1[32 * 256];       // [B, C] sigmoid self-gate
__device__ float g_w2[32 * 4 * 256];   // [B, K, C] softmax branch gates

#define B_ 32
#define C_ 256
#define K_ 4
#define HW_ 1024
#define MID_ 32
#define FEAT_ 1280   // (K+1)*C

// ---------------- Kernel 1: global average pool (R6-proven, 28.9us) ----------------
__global__ void k_means(const float* __restrict__ y,
                        const float* __restrict__ x0,
                        const float* __restrict__ x1,
                        const float* __restrict__ x2,
                        const float* __restrict__ x3) {
    int warp = (blockIdx.x * blockDim.x + threadIdx.x) >> 5;
    int lane = threadIdx.x & 31;
    int b = warp / FEAT_;
    int j = warp - b * FEAT_;       // slot*256 + c
    int slot = j >> 8;
    int c = j & 255;
    const float* base;
    switch (slot) {
        case 0: base = y;  break;
        case 1: base = x0; break;
        case 2: base = x1; break;
        case 3: base = x2; break;
        default: base = x3; break;
    }
    const float4* p = reinterpret_cast<const float4*>(base + (size_t)(b * C_ + c) * HW_);
    float s = 0.f;
#pragma unroll
    for (int i = 0; i < 8; i++) {
        float4 v = p[lane + i * 32];
        s += (v.x + v.y) + (v.z + v.w);
    }
#pragma unroll
    for (int o = 16; o; o >>= 1) s += __shfl_xor_sync(0xffffffffu, s, o);
    if (lane == 0) g_feats[warp] = s * (1.0f / 1024.0f);
}

// ---------------- Kernel 2a: GEMM1 + BN + ReLU, weight-coalesced ----------------
// One block per mid channel (32 blocks). Weight row loaded to smem BEFORE the
// grid dependency sync -> weight DRAM latency overlaps k_means' tail.
__global__ void k_gate1(const float* __restrict__ conv1_w,   // [32,1280]
                        const float* __restrict__ bn_gamma,
                        const float* __restrict__ bn_beta,
                        const float* __restrict__ bn_mean,
                        const float* __restrict__ bn_var) {
    cudaTriggerProgrammaticLaunchCompletion();   // let k_gate2 launch now

    int m = blockIdx.x;
    int t = threadIdx.x;
    __shared__ float sw[FEAT_];

    // Gate-independent: weight row + BN scalars (overlap with k_means)
    for (int i = t; i < FEAT_; i += 256) sw[i] = conv1_w[m * FEAT_ + i];
    float mean = bn_mean[m];
    float scale = bn_gamma[m] * rsqrtf(bn_var[m] + 1e-5f);
    float beta = bn_beta[m];

    cudaGridDependencySynchronize();             // wait for g_feats
    __syncthreads();

    int w = t >> 5, lane = t & 31;
    // Each of 8 warps handles 4 batches
#pragma unroll
    for (int bb = 0; bb < 4; bb++) {
        int b = w * 4 + bb;
        const float* f = g_feats + b * FEAT_;
        float s = 0.f;
#pragma unroll
        for (int k = 0; k < FEAT_ / 32; k++)
            s = fmaf(f[lane + k * 32], sw[lane + k * 32], s);
#pragma unroll
        for (int o = 16; o; o >>= 1) s += __shfl_xor_sync(0xffffffffu, s, o);
        if (lane == 0)
            g_h[m * B_ + b] = fmaxf(fmaf(s - mean, scale, beta - 0.f * beta) , 0.f) ;
    }
}

// ---------------- Kernel 2b: GEMM2 + activations, weight-coalesced ----------------
// One block per group of 8 channels (32 blocks). conv2_w slice + biases loaded
// BEFORE the sync; h loaded after. Thread (b, c_local) computes all 5 slots.
__global__ void k_gate2(const float* __restrict__ conv2_w,   // [1280,32]
                        const float* __restrict__ conv2_b) { // [1280]
    cudaTriggerProgrammaticLaunchCompletion();   // let k_apply launch now

    int cg = blockIdx.x;        // channel group: channels [cg*8, cg*8+8)
    int t = threadIdx.x;        // 256
    int c_local = t & 7;
    int b = t >> 3;

    __shared__ float sh2[5 * 8 * 33];            // [slot][c_local][mid], padded
    __shared__ float shh[MID_ * B_];             // [mid][b]

    // Gate-independent: conv2_w slice (5 x 256 contiguous floats) + biases
#pragma unroll
    for (int slot = 0; slot < 5; slot++) {
        int row = t >> 5, mid = t & 31;          // 8 rows x 32 mids = 256
        sh2[(slot * 8 + row) * 33 + mid] = conv2_w[(slot * 256 + cg * 8) * 32 + t];
    }
    float bias[5];
#pragma unroll
    for (int slot = 0; slot < 5; slot++)
        bias[slot] = conv2_b[slot * 256 + cg * 8 + c_local];

    cudaGridDependencySynchronize();             // wait for g_h
    for (int i = t; i < MID_ * B_; i += 256) shh[i] = g_h[i];
    __syncthreads();

    int c = cg * 8 + c_local;
    float v[5];
#pragma unroll
    for (int slot = 0; slot < 5; slot++) {
        float s = bias[slot];
        const float* wp = &sh2[(slot * 8 + c_local) * 33];
#pragma unroll
        for (int mid = 0; mid < MID_; mid++)
            s = fmaf(shh[mid * B_ + b], wp[mid], s);
        v[slot] = s;
    }

    g_w1[b * C_ + c] = 1.0f / (1.0f + expf(-v[0]));
    float mx = fmaxf(fmaxf(v[1], v[2]), fmaxf(v[3], v[4]));
    float e1 = expf(v[1] - mx), e2 = expf(v[2] - mx);
    float e3 = expf(v[3] - mx), e4 = expf(v[4] - mx);
    float inv = 1.0f / (e1 + e2 + e3 + e4);
    int gb = b * K_ * C_ + c;
    g_w2[gb + 0 * C_] = e1 * inv;
    g_w2[gb + 1 * C_] = e2 * inv;
    g_w2[gb + 2 * C_] = e3 * inv;
    g_w2[gb + 3 * C_] = e4 * inv;
}

// ---------------- Kernel 3: apply gates (R6-proven 30.3us, PDL) ----------------
__global__ void k_apply(const float* __restrict__ y,
                        const float* __restrict__ x0,
                        const float* __restrict__ x1,
                        const float* __restrict__ x2,
                        const float* __restrict__ x3,
                        float* __restrict__ out) {
    int blk = gridDim.x - 1 - blockIdx.x;            // reversed
    int t = threadIdx.x;
    int i0 = blk * 512 + t;
    int i1 = i0 + 256;

    const float4* Y  = reinterpret_cast<const float4*>(y);
    const float4* X0 = reinterpret_cast<const float4*>(x0);
    const float4* X1 = reinterpret_cast<const float4*>(x1);
    const float4* X2 = reinterpret_cast<const float4*>(x2);
    const float4* X3 = reinterpret_cast<const float4*>(x3);

    // Gate-independent loads first (overlap with gate kernels via PDL)
    float4 ya = Y[i0],  yb = Y[i1];
    float4 p0 = X0[i0], q0 = X0[i1];
    float4 p1 = X1[i0], q1 = X1[i1];
    float4 p2 = X2[i0], q2 = X2[i1];
    float4 p3 = X3[i0], q3 = X3[i1];

    cudaGridDependencySynchronize();

    int bc0 = blk * 2;
    int bc1 = bc0 + 1;
    int b = bc0 >> 8;
    int c0 = bc0 & 255, c1 = bc1 & 255;
    float w1a = g_w1[bc0],               w1b = g_w1[bc1];
    int ga = b * K_ * C_ + c0,           gb = b * K_ * C_ + c1;
    float a0 = g_w2[ga + 0 * C_], b0 = g_w2[gb + 0 * C_];
    float a1 = g_w2[ga + 1 * C_], b1 = g_w2[gb + 1 * C_];
    float a2 = g_w2[ga + 2 * C_], b2 = g_w2[gb + 2 * C_];
    float a3 = g_w2[ga + 3 * C_], b3 = g_w2[gb + 3 * C_];

    float4 r;
    r.x = fmaf(ya.x, w1a, fmaf(a0, p0.x, fmaf(a1, p1.x, fmaf(a2, p2.x, a3 * p3.x))));
    r.y = fmaf(ya.y, w1a, fmaf(a0, p0.y, fmaf(a1, p1.y, fmaf(a2, p2.y, a3 * p3.y))));
    r.z = fmaf(ya.z, w1a, fmaf(a0, p0.z, fmaf(a1, p1.z, fmaf(a2, p2.z, a3 * p3.z))));
    r.w = fmaf(ya.w, w1a, fmaf(a0, p0.w, fmaf(a1, p1.w, fmaf(a2, p2.w, a3 * p3.w))));
    __stcs(reinterpret_cast<float4*>(out) + i0, r);

    float4 s;
    s.x = fmaf(yb.x, w1b, fmaf(b0, q0.x, fmaf(b1, q1.x, fmaf(b2, q2.x, b3 * q3.x))));
    s.y = fmaf(yb.y, w1b, fmaf(b0, q0.y, fmaf(b1, q1.y, fmaf(b2, q2.y, b3 * q3.y))));
    s.z = fmaf(yb.z, w1b, fmaf(b0, q0.z, fmaf(b1, q1.z, fmaf(b2, q2.z, b3 * q3.z))));
    s.w = fmaf(yb.w, w1b, fmaf(b0, q0.w, fmaf(b1, q1.w, fmaf(b2, q2.w, b3 * q3.w))));
    __stcs(reinterpret_cast<float4*>(out) + i1, s);
}

extern "C" void kernel_launch(void* const* d_in, const int* in_sizes, int n_in,
                              void* d_out, int out_size) {
    const float* y       = (const float*)d_in[0];
    const float* x0      = (const float*)d_in[1];
    const float* x1      = (const float*)d_in[2];
    const float* x2      = (const float*)d_in[3];
    const float* x3      = (const float*)d_in[4];
    const float* conv1_w = (const float*)d_in[5];
    const float* bn_g    = (const float*)d_in[6];
    const float* bn_b    = (const float*)d_in[7];
    const float* bn_m    = (const float*)d_in[8];
    const float* bn_v    = (const float*)d_in[9];
    const float* conv2_w = (const float*)d_in[10];
    const float* conv2_b = (const float*)d_in[11];
    float* out = (float*)d_out;

    k_means<<<5120, 256>>>(y, x0, x1, x2, x3);

    cudaLaunchAttribute attr[1];
    attr[0].id = cudaLaunchAttributeProgrammaticStreamSerialization;
    attr[0].val.programmaticStreamSerializationAllowed = 1;

    {   // GEMM1+BN+ReLU
        cudaLaunchConfig_t cfg = {};
        cfg.gridDim = dim3(32, 1, 1);
        cfg.blockDim = dim3(256, 1, 1);
        cfg.stream = 0;
        cfg.attrs = attr;
        cfg.numAttrs = 1;
        cudaLaunchKernelEx(&cfg, k_gate1, conv1_w, bn_g, bn_b, bn_m, bn_v);
    }
    {   // GEMM2+activations
        cudaLaunchConfig_t cfg = {};
        cfg.gridDim = dim3(32, 1, 1);
        cfg.blockDim = dim3(256, 1, 1);
        cfg.stream = 0;
        cfg.attrs = attr;
        cfg.numAttrs = 1;
        cudaLaunchKernelEx(&cfg, k_gate2, conv2_w, conv2_b);
    }
    {   // apply
        cudaLaunchConfig_t cfg = {};
        cfg.gridDim = dim3(4096, 1, 1);
        cfg.blockDim = dim3(256, 1, 1);
        cfg.stream = 0;
        cfg.attrs = attr;
        cfg.numAttrs = 1;
        cudaLaunchKernelEx(&cfg, k_apply, y, x0, x1, x2, x3, out);
    }
}